// round 1
// baseline (speedup 1.0000x reference)
#include <cuda_runtime.h>

#define NB 2048   // batch
#define NS 65     // seq (1 origin + 64 walk)
#define SW 64     // walk length
#define ND 256    // IN_DIM
#define NH 8      // heads
#define NL 256    // head dim L

// Precomputed P @ Wk per head: PKbuf[h][s][l]
__device__ float PKbuf[NH * SW * NL];

__device__ __forceinline__ float sigmoidf(float x) {
    return __fdividef(1.0f, 1.0f + __expf(-x));
}

// Kernel 1: PKbuf[h][s][l] = sum_d P[s][d] * Wk[h][d][l]
__global__ void pk_kernel(const float* __restrict__ P, const float* __restrict__ Wk) {
    const int s = blockIdx.x, h = blockIdx.y, l = threadIdx.x;
    __shared__ float Ps[ND];
    Ps[l] = P[s * ND + l];
    __syncthreads();
    const float* wk = Wk + (size_t)h * ND * NL + l;
    float a0 = 0.f, a1 = 0.f, a2 = 0.f, a3 = 0.f;
#pragma unroll 4
    for (int d = 0; d < ND; d += 4) {
        a0 = fmaf(Ps[d + 0], wk[(d + 0) * NL], a0);
        a1 = fmaf(Ps[d + 1], wk[(d + 1) * NL], a1);
        a2 = fmaf(Ps[d + 2], wk[(d + 2) * NL], a2);
        a3 = fmaf(Ps[d + 3], wk[(d + 3) * NL], a3);
    }
    PKbuf[((size_t)h * SW + s) * NL + l] = (a0 + a1) + (a2 + a3);
}

// Kernel 2: one CTA per batch row. Thread = column l (0..255).
__global__ __launch_bounds__(256, 2)
void wattn_kernel(const float* __restrict__ x,
                  const float* __restrict__ Wq,
                  const float* __restrict__ Wk,
                  const float* __restrict__ Wv,
                  const float* __restrict__ Wvec,   // W[h][l][0] -> [NH*NL]
                  const float* __restrict__ Omat,   // [NH*NL][ND]
                  const float* __restrict__ bias,   // [NH]
                  float* __restrict__ out)          // [NB][2*ND]
{
    extern __shared__ float sm[];
    float* walk     = sm;                    // [SW][ND]  64 KB
    float* origin   = walk + SW * ND;        // [ND]
    float* resall   = origin + ND;           // [NH*NL]   8 KB
    float* scorebuf = resall + NH * NL;      // [SW]
    float* partial  = scorebuf + SW;         // [SW][8]

    const int b = blockIdx.x;
    const int l = threadIdx.x;
    const int warp = l >> 5, lane = l & 31;

    // Load x row: origin + walk (coalesced; walk[s][d] layout matches gmem)
    const float* xb = x + (size_t)b * NS * ND;
    origin[l] = xb[l];
#pragma unroll
    for (int e = 0; e < SW * ND; e += 256) walk[e + l] = xb[ND + e + l];
    __syncthreads();

    for (int h = 0; h < NH; h++) {
        // --- k-logit base: OK[l] = sum_d origin[d] * Wk[h][d][l] ---
        const float* wk = Wk + (size_t)h * ND * NL + l;
        float k0 = 0.f, k1 = 0.f, k2 = 0.f, k3 = 0.f;
#pragma unroll 4
        for (int d = 0; d < ND; d += 4) {
            k0 = fmaf(origin[d + 0], wk[(d + 0) * NL], k0);
            k1 = fmaf(origin[d + 1], wk[(d + 1) * NL], k1);
            k2 = fmaf(origin[d + 2], wk[(d + 2) * NL], k2);
            k3 = fmaf(origin[d + 3], wk[(d + 3) * NL], k3);
        }
        const float okl = (k0 + k1) + (k2 + k3);
        const float wl = Wvec[h * NL + l];
        const float bh = bias[h];

        // --- q-pass: 2 chunks of 32 s-rows; edge -> score partials ---
#pragma unroll
        for (int c = 0; c < 2; c++) {
            float acc[32];
#pragma unroll
            for (int i = 0; i < 32; i++) acc[i] = 0.f;
            const float* wq = Wq + (size_t)h * ND * NL + l;
            const float* wrow = walk + c * 32 * ND;
#pragma unroll 4
            for (int d = 0; d < ND; d++) {
                const float w = wq[d * NL];            // coalesced LDG, L2-resident
#pragma unroll
                for (int i = 0; i < 32; i++)           // broadcast LDS, conflict-free
                    acc[i] = fmaf(wrow[i * ND + d], w, acc[i]);
            }
#pragma unroll
            for (int i = 0; i < 32; i++) {
                const int s = c * 32 + i;
                const float q  = sigmoidf(acc[i]);
                const float kk = sigmoidf(okl + PKbuf[((size_t)h * SW + s) * NL + l]);
                float contrib = (__cosf(kk * q) + bh) * wl;
#pragma unroll
                for (int o = 16; o > 0; o >>= 1)
                    contrib += __shfl_xor_sync(0xffffffffu, contrib, o);
                if (lane == 0) partial[s * 8 + warp] = contrib;
            }
        }
        __syncthreads();

        // --- softmax over s (warp 0, 2 scores per lane) ---
        if (warp == 0) {
            float sc0 = 0.f, sc1 = 0.f;
#pragma unroll
            for (int w = 0; w < 8; w++) {
                sc0 += partial[lane * 8 + w];
                sc1 += partial[(lane + 32) * 8 + w];
            }
            float m = fmaxf(sc0, sc1);
#pragma unroll
            for (int o = 16; o > 0; o >>= 1)
                m = fmaxf(m, __shfl_xor_sync(0xffffffffu, m, o));
            const float e0 = __expf(sc0 - m);
            const float e1 = __expf(sc1 - m);
            float ssum = e0 + e1;
#pragma unroll
            for (int o = 16; o > 0; o >>= 1)
                ssum += __shfl_xor_sync(0xffffffffu, ssum, o);
            const float inv = __fdividef(1.f, ssum);
            scorebuf[lane]      = e0 * inv;
            scorebuf[lane + 32] = e1 * inv;
        }
        __syncthreads();

        // --- v-pass: fold sigmoid(v) directly into res (no v storage) ---
        float r = 0.f;
#pragma unroll
        for (int c = 0; c < 2; c++) {
            float acc[32];
#pragma unroll
            for (int i = 0; i < 32; i++) acc[i] = 0.f;
            const float* wv = Wv + (size_t)h * ND * NL + l;
            const float* wrow = walk + c * 32 * ND;
#pragma unroll 4
            for (int d = 0; d < ND; d++) {
                const float w = wv[d * NL];
#pragma unroll
                for (int i = 0; i < 32; i++)
                    acc[i] = fmaf(wrow[i * ND + d], w, acc[i]);
            }
#pragma unroll
            for (int i = 0; i < 32; i++)
                r = fmaf(sigmoidf(acc[i]), scorebuf[c * 32 + i], r);
        }
        resall[h * NL + l] = r;
        __syncthreads();
    }

    // --- final projection: out[l] = sigmoid(sum_i resall[i] * O[i][l]) ---
    const float* Ob = Omat + l;
    float a0 = 0.f, a1 = 0.f, a2 = 0.f, a3 = 0.f;
#pragma unroll 8
    for (int i = 0; i < NH * NL; i += 4) {
        a0 = fmaf(resall[i + 0], Ob[(size_t)(i + 0) * ND], a0);
        a1 = fmaf(resall[i + 1], Ob[(size_t)(i + 1) * ND], a1);
        a2 = fmaf(resall[i + 2], Ob[(size_t)(i + 2) * ND], a2);
        a3 = fmaf(resall[i + 3], Ob[(size_t)(i + 3) * ND], a3);
    }
    const float o = sigmoidf((a0 + a1) + (a2 + a3));
    float* ob = out + (size_t)b * (2 * ND);
    ob[l]      = o;
    ob[ND + l] = origin[l];
}

static const int SMEM_BYTES = (SW * ND + ND + NH * NL + SW + SW * 8) * (int)sizeof(float);

extern "C" void kernel_launch(void* const* d_in, const int* in_sizes, int n_in,
                              void* d_out, int out_size) {
    const float* x    = (const float*)d_in[0];
    const float* Wq   = (const float*)d_in[1];
    const float* Wk   = (const float*)d_in[2];
    const float* Wv   = (const float*)d_in[3];
    const float* W    = (const float*)d_in[4];
    const float* Omat = (const float*)d_in[5];
    const float* P    = (const float*)d_in[6];
    const float* bias = (const float*)d_in[7];
    float* out = (float*)d_out;

    (void)in_sizes; (void)n_in; (void)out_size;

    dim3 g1(SW, NH);
    pk_kernel<<<g1, 256>>>(P, Wk);

    cudaFuncSetAttribute(wattn_kernel, cudaFuncAttributeMaxDynamicSharedMemorySize, SMEM_BYTES);
    wattn_kernel<<<NB, 256, SMEM_BYTES>>>(x, Wq, Wk, Wv, W, Omat, bias, out);
}